// round 1
// baseline (speedup 1.0000x reference)
#include <cuda_runtime.h>
#include <cuda_bf16.h>

// KAN layer: y[b,o] = sum_f lerp(coeff[f, idx-1, o], coeff[f, idx, o], t) + bias[o]
// B=4096, F=128 (IN_DIM), G=64 (GRID_SIZE), OUT=64.
// Grid = linspace(-3, 3, 64) -> spacing h = 6/63, inv_h = 10.5.
// searchsorted(g, x, 'left') clipped to [1,63]:  i = clip(ceil((x+3)*inv_h), 1, 63)
// t = (x - g[i-1]) / h = (x+3)*inv_h - (i-1)   (NOT clamped: reference extrapolates)

#define F_DIM   128
#define G_SIZE  64
#define OUT_N   64
#define SPB     16          // samples per block
#define THREADS 256         // 16 samples x 16 threads; each thread owns 4 outputs

__global__ __launch_bounds__(THREADS, 4)
void kan_gather_kernel(const float* __restrict__ x,
                       const float* __restrict__ coeff,
                       const float* __restrict__ bias,
                       float* __restrict__ y)
{
    __shared__ float xs[SPB * F_DIM];   // 8 KB x-tile, broadcast-read in main loop

    const int tid = threadIdx.x;
    const int row0 = blockIdx.x * SPB;

    // Coalesced load of the x tile: 16 rows x 128 floats = 512 float4s, 256 threads.
    {
        const float4* xg = reinterpret_cast<const float4*>(x + row0 * F_DIM);
        float4* xs4 = reinterpret_cast<float4*>(xs);
        #pragma unroll
        for (int i = 0; i < (SPB * F_DIM / 4) / THREADS; ++i)
            xs4[tid + i * THREADS] = xg[tid + i * THREADS];
    }
    __syncthreads();

    const int s    = tid >> 4;     // local sample 0..15
    const int lane = tid & 15;     // 0..15
    const int o4   = lane << 2;    // output base (float4)

    const float inv_h = 10.5f;     // 63/6
    const float* xrow = xs + s * F_DIM;

    float4 acc = make_float4(0.f, 0.f, 0.f, 0.f);

    #pragma unroll 4
    for (int f = 0; f < F_DIM; ++f) {
        const float xv = xrow[f];
        const float u  = (xv + 3.0f) * inv_h;
        int i = (int)ceilf(u);
        i = max(1, min(i, G_SIZE - 1));
        const float t = u - (float)(i - 1);

        // coeff[f, i-1, o4..o4+3] and coeff[f, i, o4..o4+3]
        const float* p = coeff + ((f * G_SIZE + (i - 1)) * OUT_N) + o4;
        const float4 c0 = *reinterpret_cast<const float4*>(p);
        const float4 c1 = *reinterpret_cast<const float4*>(p + OUT_N);

        // (1-t)*c0 + t*c1 = c0 + t*(c1-c0)
        acc.x += c0.x + t * (c1.x - c0.x);
        acc.y += c0.y + t * (c1.y - c0.y);
        acc.z += c0.z + t * (c1.z - c0.z);
        acc.w += c0.w + t * (c1.w - c0.w);
    }

    const float4 bv = *reinterpret_cast<const float4*>(bias + o4);
    acc.x += bv.x; acc.y += bv.y; acc.z += bv.z; acc.w += bv.w;

    *reinterpret_cast<float4*>(y + (row0 + s) * OUT_N + o4) = acc;
}

extern "C" void kernel_launch(void* const* d_in, const int* in_sizes, int n_in,
                              void* d_out, int out_size)
{
    const float* x     = (const float*)d_in[0];   // [4096, 128]
    const float* coeff = (const float*)d_in[1];   // [128, 64, 64]
    const float* bias  = (const float*)d_in[2];   // [64]
    float* y           = (float*)d_out;           // [4096, 64]

    const int n_samples = in_sizes[0] / F_DIM;    // 4096
    const int blocks = n_samples / SPB;           // 256

    kan_gather_kernel<<<blocks, THREADS>>>(x, coeff, bias, y);
}

// round 2
// speedup vs baseline: 1.0511x; 1.0511x over previous
#include <cuda_runtime.h>
#include <cuda_bf16.h>

// KAN layer: y[b,o] = sum_f lerp(coeff[f, idx-1, o], coeff[f, idx, o], t) + bias[o]
// B=4096, F=128, G=64, OUT=64.  grid = linspace(-3,3,64), h = 6/63, inv_h = 10.5
// searchsorted 'left' clipped to [1,63]: i = clip(ceil((x+3)*10.5), 1, 63)
// t = (x+3)*10.5 - (i-1)   (unclamped: reference extrapolates)
//
// R1: split the F loop 4 ways per sample to fix occupancy (21% -> ~85%).
// Layout: 256 threads = 4 samples x 4 f-groups x 16 lanes; each thread owns
// 4 outputs (float4) and 32 features; partials reduced via smem.

#define F_DIM   128
#define G_SIZE  64
#define OUT_N   64
#define SPB     4           // samples per block
#define FGROUPS 4
#define F_PER_T (F_DIM / FGROUPS)   // 32
#define THREADS 256

__global__ __launch_bounds__(THREADS)
void kan_split_kernel(const float* __restrict__ x,
                      const float* __restrict__ coeff,
                      const float* __restrict__ bias,
                      float* __restrict__ y)
{
    __shared__ float  xs[SPB * F_DIM];      // 2 KB x tile
    __shared__ float4 part[THREADS];        // 4 KB partial sums

    const int tid  = threadIdx.x;
    const int row0 = blockIdx.x * SPB;

    // Load x tile: 4 rows x 128 floats = 128 float4s
    if (tid < SPB * F_DIM / 4) {
        reinterpret_cast<float4*>(xs)[tid] =
            reinterpret_cast<const float4*>(x + row0 * F_DIM)[tid];
    }
    __syncthreads();

    const int lane = tid & 15;          // 0..15 -> output slice
    const int fg   = (tid >> 4) & 3;    // 0..3  -> feature group
    const int s    = tid >> 6;          // 0..3  -> local sample
    const int o4   = lane << 2;

    const float inv_h = 10.5f;
    const float* xrow = xs + s * F_DIM + fg * F_PER_T;
    const float* cbase = coeff + (fg * F_PER_T) * (G_SIZE * OUT_N) + o4;

    float4 acc = make_float4(0.f, 0.f, 0.f, 0.f);

    #pragma unroll 8
    for (int f = 0; f < F_PER_T; ++f) {
        const float xv = xrow[f];
        const float u  = (xv + 3.0f) * inv_h;
        int i = (int)ceilf(u);
        i = max(1, min(i, G_SIZE - 1));
        const float t = u - (float)(i - 1);

        const float* p = cbase + (f * G_SIZE + (i - 1)) * OUT_N;
        const float4 c0 = *reinterpret_cast<const float4*>(p);
        const float4 c1 = *reinterpret_cast<const float4*>(p + OUT_N);

        acc.x += c0.x + t * (c1.x - c0.x);
        acc.y += c0.y + t * (c1.y - c0.y);
        acc.z += c0.z + t * (c1.z - c0.z);
        acc.w += c0.w + t * (c1.w - c0.w);
    }

    part[tid] = acc;
    __syncthreads();

    // fg==0 threads (tid % 64 < 16) reduce the 4 partials and store.
    if (fg == 0) {
        const float4 p1 = part[tid + 16];
        const float4 p2 = part[tid + 32];
        const float4 p3 = part[tid + 48];
        const float4 bv = *reinterpret_cast<const float4*>(bias + o4);

        acc.x += p1.x + p2.x + p3.x + bv.x;
        acc.y += p1.y + p2.y + p3.y + bv.y;
        acc.z += p1.z + p2.z + p3.z + bv.z;
        acc.w += p1.w + p2.w + p3.w + bv.w;

        *reinterpret_cast<float4*>(y + (row0 + s) * OUT_N + o4) = acc;
    }
}

extern "C" void kernel_launch(void* const* d_in, const int* in_sizes, int n_in,
                              void* d_out, int out_size)
{
    const float* x     = (const float*)d_in[0];   // [4096, 128]
    const float* coeff = (const float*)d_in[1];   // [128, 64, 64]
    const float* bias  = (const float*)d_in[2];   // [64]
    float* y           = (float*)d_out;           // [4096, 64]

    const int n_samples = in_sizes[0] / F_DIM;    // 4096
    const int blocks = n_samples / SPB;           // 1024

    kan_split_kernel<<<blocks, THREADS>>>(x, coeff, bias, y);
}